// round 12
// baseline (speedup 1.0000x reference)
#include <cuda_runtime.h>
#include <cuda_fp16.h>
#include <math.h>
#include <stdint.h>

// ============================================================================
// Decoder_33208687133135 — Round 12: gemm23 at 512 threads / 16 warps,
// warp tile 32x32, 50% occupancy (latency-bound fix per R11 ncu).
// rows r (per MLP, 131072): Z[r][l] = koopman[r>>6][l][r&63]
// h1=tanh(Z W1+b1); h2=tanh(h1 W2+b2); h3=tanh(h2 W3+b3); diag=h3.W4[:,r&63]
// out = (x - dt) * exp(-ds)
// ============================================================================

#define HALF_M 131072
#define MTOT   262144

// ---- static scratch --------------------------------------------------------
__device__ __half g_zh[(size_t)HALF_M * 64];
__device__ __half g_zl[(size_t)HALF_M * 64];
__device__ __half g_w1h[2][512 * 64];            // [mlp], W1^T [n][k] fp16
__device__ __half g_w23h[4][512 * 512];          // [mlp*2+layer], W^T [n][k] fp16
__device__ float  g_w4t[2][64 * 512];            // [mlp], W4^T [i][k]
__device__ __half g_h1[(size_t)MTOT * 512];
__device__ __half g_h2[(size_t)MTOT * 512];
__device__ float  g_part[16][MTOT];              // diag partials per 32-n slice

// ---- PTX helpers -----------------------------------------------------------
#define CP16(d, s) asm volatile("cp.async.cg.shared.global [%0], [%1], 16;" :: "r"(d), "l"(s))
#define CP_COMMIT  asm volatile("cp.async.commit_group;")
#define CP_WAIT(n) asm volatile("cp.async.wait_group %0;" :: "n"(n) : "memory")

#define LDSM4(R, addr)                                                         \
    asm volatile("ldmatrix.sync.aligned.m8n8.x4.shared.b16 {%0,%1,%2,%3}, [%4];" \
        : "=r"(R[0]), "=r"(R[1]), "=r"(R[2]), "=r"(R[3]) : "r"(addr))

#define MMA(d, a, b0, b1)                                                      \
    asm volatile("mma.sync.aligned.m16n8k16.row.col.f32.f16.f16.f32 "          \
        "{%0,%1,%2,%3},{%4,%5,%6,%7},{%8,%9},{%0,%1,%2,%3};"                   \
        : "+f"(d[0]), "+f"(d[1]), "+f"(d[2]), "+f"(d[3])                       \
        : "r"(a[0]), "r"(a[1]), "r"(a[2]), "r"(a[3]), "r"(b0), "r"(b1))

// ============================================================================
// prep kernels (2 launches)
// ============================================================================
__global__ __launch_bounds__(256) void prep_z(const float* __restrict__ koop)
{
    __shared__ float s[64][65];
    int b = blockIdx.x;
    const float* src = koop + (size_t)b * 4096;
    for (int e = threadIdx.x; e < 4096; e += 256) {
        int l = e >> 6, i = e & 63;
        s[i][l] = src[e];
    }
    __syncthreads();
    for (int e = threadIdx.x; e < 4096; e += 256) {
        int i = e >> 6, l = e & 63;
        float v = s[i][l];
        __half h = __float2half_rn(v);
        size_t o = (size_t)(b * 64 + i) * 64 + l;
        g_zh[o] = h;
        g_zl[o] = __float2half_rn(v - __half2float(h));
    }
}

__device__ __forceinline__ void tsp_tile(const float* __restrict__ W, int K, int N,
                                         __half* __restrict__ oh)
{
    __shared__ float t[32][33];
    int tx = threadIdx.x, ty = threadIdx.y;
    int k0 = blockIdx.x * 32, n0 = blockIdx.y * 32;
#pragma unroll
    for (int j = 0; j < 4; j++)
        t[ty + j * 8][tx] = W[(size_t)(k0 + ty + j * 8) * N + n0 + tx];
    __syncthreads();
#pragma unroll
    for (int j = 0; j < 4; j++) {
        int n = n0 + ty + j * 8;
        oh[(size_t)n * K + k0 + tx] = __float2half_rn(t[tx][ty + j * 8]);
    }
}

__global__ void prep_w(const float* sW1, const float* sW2, const float* sW3,
                       const float* sW4, const float* tW1, const float* tW2,
                       const float* tW3, const float* tW4)
{
    int z = blockIdx.z;
    if (z < 4) {
        const float* W = (z == 0) ? sW2 : (z == 1) ? sW3 : (z == 2) ? tW2 : tW3;
        tsp_tile(W, 512, 512, g_w23h[z]);
    } else if (z < 6) {
        if (blockIdx.x >= 2) return;
        int mlp = z - 4;
        tsp_tile(mlp ? tW1 : sW1, 64, 512, g_w1h[mlp]);
    } else {
        int tid = threadIdx.y * 32 + threadIdx.x;
        int e = (blockIdx.y * 16 + blockIdx.x) * 256 + tid;   // 65536
        int mlp = e >> 15, rem = e & 32767;
        int i = rem >> 9, k = rem & 511;
        g_w4t[mlp][i * 512 + k] = (mlp ? tW4 : sW4)[(size_t)k * 64 + i];
    }
}

// ============================================================================
// smem layout (halves, stride 72): stage = A[128][72] | B[128][72]; x3 ring
// ============================================================================
#define ST_BYTES 36864
#define B_OFF    18432
#define G23_BIAS (3 * ST_BYTES)
#define G23_SMEM (3 * ST_BYTES + 512)
// gemm_l1: Ah @0, Al @18432, Bh @36864, bias @55296
#define L1_SMEM  55808

// ============================================================================
// gemm23: C = tanh(A @ W^T + b). 512 threads, 16 warps (4m x 4n), warp 32x32.
// 3-stage cp.async ring, one sync per stage. grid (4 nCTA, 2048 mCTA).
// ============================================================================
__global__ __launch_bounds__(512, 2) void gemm23(
    int layer, int is_l3,
    const float* __restrict__ bias_s, const float* __restrict__ bias_t)
{
    extern __shared__ uint8_t smem[];
    const uint32_t sb = (uint32_t)__cvta_generic_to_shared(smem);
    const int tid = threadIdx.x, lane = tid & 31, wid = tid >> 5;
    const int wm = wid >> 2, wn = wid & 3;        // 4 x 4 warps
    const int grp = lane >> 2, q = lane & 3;
    const int n0 = blockIdx.x * 128;
    const int m0 = blockIdx.y * 128;
    const int mlp = (blockIdx.y >= 1024) ? 1 : 0;
    const __half* A  = layer ? g_h2 : g_h1;
    __half* O        = g_h2;                      // only used when !is_l3
    const __half* Wh = g_w23h[mlp * 2 + layer];

    if (tid < 128)
        ((float*)(smem + G23_BIAS))[tid] = (mlp ? bias_t : bias_s)[n0 + tid];

    auto load_stage = [&](uint32_t base, int k0) {
#pragma unroll
        for (int i = 0; i < 2; i++) {
            int c = tid + i * 512;
            int r = c >> 3, kc = (c & 7) << 3;
            CP16(base + (r * 72 + kc) * 2, A + (size_t)(m0 + r) * 512 + k0 + kc);
        }
#pragma unroll
        for (int i = 0; i < 2; i++) {
            int c = tid + i * 512;
            int n = c >> 3, kc = (c & 7) << 3;
            CP16(base + B_OFF + (n * 72 + kc) * 2,
                 Wh + (size_t)(n0 + n) * 512 + k0 + kc);
        }
        CP_COMMIT;
    };

    float acc[2][4][4];
#pragma unroll
    for (int a = 0; a < 2; a++)
#pragma unroll
        for (int b = 0; b < 4; b++)
#pragma unroll
            for (int c = 0; c < 4; c++) acc[a][b][c] = 0.f;

    uint32_t offA[2], offB[2];
#pragma unroll
    for (int mi = 0; mi < 2; ++mi)
        offA[mi] = ((wm * 32 + mi * 16 + (lane & 15)) * 72 + (lane >> 4) * 8) * 2;
#pragma unroll
    for (int j = 0; j < 2; ++j)
        offB[j] = B_OFF +
            ((wn * 32 + j * 16 + (lane & 7) + ((lane >> 4) << 3)) * 72 +
             ((lane >> 3) & 1) * 8) * 2;

    load_stage(sb, 0);
    load_stage(sb + ST_BYTES, 64);
#pragma unroll 1
    for (int s = 0; s < 8; ++s) {
        if (s < 7) CP_WAIT(1); else CP_WAIT(0);
        __syncthreads();
        if (s < 6) load_stage(sb + ((s + 2) % 3) * ST_BYTES, (s + 2) * 64);
        uint32_t cur = sb + (s % 3) * ST_BYTES;
#pragma unroll
        for (int ks = 0; ks < 64; ks += 16) {
            uint32_t a0[4], a1[4];
            LDSM4(a0, cur + offA[0] + ks * 2);
            LDSM4(a1, cur + offA[1] + ks * 2);
#pragma unroll
            for (int j = 0; j < 2; ++j) {
                uint32_t b[4];
                LDSM4(b, cur + offB[j] + ks * 2);
                MMA(acc[0][j * 2],     a0, b[0], b[1]);
                MMA(acc[0][j * 2 + 1], a0, b[2], b[3]);
                MMA(acc[1][j * 2],     a1, b[0], b[1]);
                MMA(acc[1][j * 2 + 1], a1, b[2], b[3]);
            }
        }
    }
    __syncthreads();

    const float* sbias = (const float*)(smem + G23_BIAS);
    if (!is_l3) {
#pragma unroll
        for (int mi = 0; mi < 2; ++mi)
#pragma unroll
        for (int nj = 0; nj < 4; ++nj) {
            int row = m0 + wm * 32 + mi * 16 + grp;
            int cl  = wn * 32 + nj * 8 + q * 2;
            float b0 = sbias[cl], b1 = sbias[cl + 1];
            float v00 = tanhf(acc[mi][nj][0] + b0);
            float v01 = tanhf(acc[mi][nj][1] + b1);
            float v10 = tanhf(acc[mi][nj][2] + b0);
            float v11 = tanhf(acc[mi][nj][3] + b1);
            size_t o0 = (size_t)row * 512 + n0 + cl;
            *reinterpret_cast<__half2*>(O + o0) =
                __halves2half2(__float2half_rn(v00), __float2half_rn(v01));
            *reinterpret_cast<__half2*>(O + o0 + 8 * 512) =
                __halves2half2(__float2half_rn(v10), __float2half_rn(v11));
        }
    } else {
        // stage W4^T slice [64 i][128 n] fp32 into dead ring area
        float* sw4 = (float*)smem;
        for (int e = tid; e < 8192; e += 512) {
            int i = e >> 7, c = e & 127;
            sw4[i * 129 + c] = g_w4t[mlp][i * 512 + n0 + c];
        }
        __syncthreads();
        const int iA = (wm * 32 + grp) & 63;
        float ps[2][2];
        ps[0][0] = ps[0][1] = ps[1][0] = ps[1][1] = 0.f;
#pragma unroll
        for (int mi = 0; mi < 2; ++mi)
#pragma unroll
        for (int nj = 0; nj < 4; ++nj) {
            int cl = wn * 32 + nj * 8 + q * 2;
            float b0 = sbias[cl], b1 = sbias[cl + 1];
            int i0 = (iA + mi * 16) & 63, i1 = (iA + mi * 16 + 8) & 63;
            ps[mi][0] += tanhf(acc[mi][nj][0] + b0) * sw4[i0 * 129 + cl]
                       + tanhf(acc[mi][nj][1] + b1) * sw4[i0 * 129 + cl + 1];
            ps[mi][1] += tanhf(acc[mi][nj][2] + b0) * sw4[i1 * 129 + cl]
                       + tanhf(acc[mi][nj][3] + b1) * sw4[i1 * 129 + cl + 1];
        }
        int slice = blockIdx.x * 4 + wn;
#pragma unroll
        for (int mi = 0; mi < 2; ++mi)
#pragma unroll
        for (int rh = 0; rh < 2; ++rh) {
            float v = ps[mi][rh];
            v += __shfl_xor_sync(0xffffffffu, v, 1);
            v += __shfl_xor_sync(0xffffffffu, v, 2);
            if (q == 0)
                g_part[slice][m0 + wm * 32 + mi * 16 + rh * 8 + grp] = v;
        }
    }
}

// ============================================================================
// gemm_l1: K=64, Z split (Zh+Zl, 2 products), W1 fp16. grid (4, 2048).
// ============================================================================
__global__ __launch_bounds__(256, 2) void gemm_l1(
    const float* __restrict__ b1s, const float* __restrict__ b1t)
{
    extern __shared__ uint8_t smem[];
    const uint32_t sb = (uint32_t)__cvta_generic_to_shared(smem);
    const int tid = threadIdx.x, lane = tid & 31, wid = tid >> 5;
    const int wm = wid >> 2, wn = wid & 3;
    const int grp = lane >> 2, q = lane & 3;
    const int n0 = blockIdx.x * 128;
    const int mlp = (blockIdx.y >= 1024) ? 1 : 0;
    const int zrow0 = (blockIdx.y & 1023) * 128;
    const int m0 = blockIdx.y * 128;

    if (tid < 128)
        ((float*)(smem + 55296))[tid] = (mlp ? b1t : b1s)[n0 + tid];

#pragma unroll
    for (int i = 0; i < 8; i++) {
        int c = tid + i * 256;
        int hl = c >> 10, cc = c & 1023;
        int r = cc >> 3, kc = (cc & 7) << 3;
        const __half* src = (hl ? g_zl : g_zh) + (size_t)(zrow0 + r) * 64 + kc;
        CP16(sb + hl * 18432 + (r * 72 + kc) * 2, src);
    }
#pragma unroll
    for (int i = 0; i < 4; i++) {
        int c = tid + i * 256;
        int n = c >> 3, kc = (c & 7) << 3;
        CP16(sb + 36864 + (n * 72 + kc) * 2,
             g_w1h[mlp] + (size_t)(n0 + n) * 64 + kc);
    }
    CP_COMMIT; CP_WAIT(0);
    __syncthreads();

    float acc[4][4][4];
#pragma unroll
    for (int a = 0; a < 4; a++)
#pragma unroll
        for (int b = 0; b < 4; b++)
#pragma unroll
            for (int c = 0; c < 4; c++) acc[a][b][c] = 0.f;

    uint32_t offA[4], offB[2];
#pragma unroll
    for (int mi = 0; mi < 4; ++mi)
        offA[mi] = ((wm * 64 + mi * 16 + (lane & 15)) * 72 + (lane >> 4) * 8) * 2;
#pragma unroll
    for (int j = 0; j < 2; ++j)
        offB[j] = 36864 +
            ((wn * 32 + j * 16 + (lane & 7) + ((lane >> 4) << 3)) * 72 +
             ((lane >> 3) & 1) * 8) * 2;

#pragma unroll
    for (int ks = 0; ks < 64; ks += 16) {
        uint32_t ah[4][4], al[4][4];
#pragma unroll
        for (int mi = 0; mi < 4; ++mi) {
            LDSM4(ah[mi], sb + offA[mi] + ks * 2);
            LDSM4(al[mi], sb + 18432 + offA[mi] + ks * 2);
        }
#pragma unroll
        for (int j = 0; j < 2; ++j) {
            uint32_t b[4];
            LDSM4(b, sb + offB[j] + ks * 2);
#pragma unroll
            for (int mi = 0; mi < 4; ++mi) {
                MMA(acc[mi][j * 2],     ah[mi], b[0], b[1]);
                MMA(acc[mi][j * 2],     al[mi], b[0], b[1]);
                MMA(acc[mi][j * 2 + 1], ah[mi], b[2], b[3]);
                MMA(acc[mi][j * 2 + 1], al[mi], b[2], b[3]);
            }
        }
    }

    const float* sbias = (const float*)(smem + 55296);
#pragma unroll
    for (int mi = 0; mi < 4; ++mi)
#pragma unroll
    for (int nj = 0; nj < 4; ++nj) {
        int row = m0 + wm * 64 + mi * 16 + grp;
        int cl  = wn * 32 + nj * 8 + q * 2;
        float b0 = sbias[cl], b1 = sbias[cl + 1];
        float v00 = tanhf(acc[mi][nj][0] + b0);
        float v01 = tanhf(acc[mi][nj][1] + b1);
        float v10 = tanhf(acc[mi][nj][2] + b0);
        float v11 = tanhf(acc[mi][nj][3] + b1);
        size_t o0 = (size_t)row * 512 + n0 + cl;
        *reinterpret_cast<__half2*>(g_h1 + o0) =
            __halves2half2(__float2half_rn(v00), __float2half_rn(v01));
        *reinterpret_cast<__half2*>(g_h1 + o0 + 8 * 512) =
            __halves2half2(__float2half_rn(v10), __float2half_rn(v11));
    }
}

// ============================================================================
__global__ __launch_bounds__(256) void final_k(
    const float* __restrict__ x, const float* __restrict__ sb4,
    const float* __restrict__ tb4, float* __restrict__ out)
{
    int r = blockIdx.x * 256 + threadIdx.x;
    int i = r & 63;
    float ds = sb4[i], dt = tb4[i];
#pragma unroll
    for (int s = 0; s < 16; s++) {
        ds += g_part[s][r];
        dt += g_part[s][HALF_M + r];
    }
    out[r] = (x[r] - dt) * expf(-ds);
}

// ============================================================================
extern "C" void kernel_launch(void* const* d_in, const int* in_sizes, int n_in,
                              void* d_out, int out_size)
{
    (void)in_sizes; (void)n_in; (void)out_size;
    const float* x    = (const float*)d_in[0];
    const float* koop = (const float*)d_in[1];
    const float* sW1 = (const float*)d_in[2];  const float* sb1 = (const float*)d_in[3];
    const float* sW2 = (const float*)d_in[4];  const float* sb2 = (const float*)d_in[5];
    const float* sW3 = (const float*)d_in[6];  const float* sb3 = (const float*)d_in[7];
    const float* sW4 = (const float*)d_in[8];  const float* sb4 = (const float*)d_in[9];
    const float* tW1 = (const float*)d_in[10]; const float* tb1 = (const float*)d_in[11];
    const float* tW2 = (const float*)d_in[12]; const float* tb2 = (const float*)d_in[13];
    const float* tW3 = (const float*)d_in[14]; const float* tb3 = (const float*)d_in[15];
    const float* tW4 = (const float*)d_in[16]; const float* tb4 = (const float*)d_in[17];
    float* out = (float*)d_out;

    static int done = 0;
    if (!done) {
        cudaFuncSetAttribute(gemm23, cudaFuncAttributeMaxDynamicSharedMemorySize, G23_SMEM);
        cudaFuncSetAttribute(gemm_l1, cudaFuncAttributeMaxDynamicSharedMemorySize, L1_SMEM);
        done = 1;
    }

    prep_z<<<2048, 256>>>(koop);
    prep_w<<<dim3(16, 16, 7), dim3(32, 8)>>>(sW1, sW2, sW3, sW4,
                                             tW1, tW2, tW3, tW4);

    dim3 grid(4, 2048);
    gemm_l1<<<grid, 256, L1_SMEM>>>(sb1, tb1);
    gemm23 <<<grid, 512, G23_SMEM>>>(0, 0, sb2, tb2);
    gemm23 <<<grid, 512, G23_SMEM>>>(1, 1, sb3, tb3);
    final_k<<<512, 256>>>(x, sb4, tb4, out);
}

// round 13
// speedup vs baseline: 1.0105x; 1.0105x over previous
#include <cuda_runtime.h>
#include <cuda_fp16.h>
#include <math.h>
#include <stdint.h>

// ============================================================================
// Decoder_33208687133135 — Round 13: register-fragment double buffering in
// gemm23 (hide LDSM latency under MMA; fix R11/R12 dependency bubbles).
// rows r (per MLP, 131072): Z[r][l] = koopman[r>>6][l][r&63]
// h1=tanh(Z W1+b1); h2=tanh(h1 W2+b2); h3=tanh(h2 W3+b3); diag=h3.W4[:,r&63]
// out = (x - dt) * exp(-ds)
// ============================================================================

#define HALF_M 131072
#define MTOT   262144

// ---- static scratch --------------------------------------------------------
__device__ __half g_zh[(size_t)HALF_M * 64];
__device__ __half g_zl[(size_t)HALF_M * 64];
__device__ __half g_w1h[2][512 * 64];            // [mlp], W1^T [n][k] fp16
__device__ __half g_w23h[4][512 * 512];          // [mlp*2+layer], W^T [n][k] fp16
__device__ float  g_w4t[2][64 * 512];            // [mlp], W4^T [i][k]
__device__ __half g_h1[(size_t)MTOT * 512];
__device__ __half g_h2[(size_t)MTOT * 512];
__device__ float  g_part[16][MTOT];              // diag partials per 32-n slice

// ---- PTX helpers -----------------------------------------------------------
#define CP16(d, s) asm volatile("cp.async.cg.shared.global [%0], [%1], 16;" :: "r"(d), "l"(s))
#define CP_COMMIT  asm volatile("cp.async.commit_group;")
#define CP_WAIT(n) asm volatile("cp.async.wait_group %0;" :: "n"(n) : "memory")

#define LDSM4(R, addr)                                                         \
    asm volatile("ldmatrix.sync.aligned.m8n8.x4.shared.b16 {%0,%1,%2,%3}, [%4];" \
        : "=r"(R[0]), "=r"(R[1]), "=r"(R[2]), "=r"(R[3]) : "r"(addr))

#define MMA(d, a, b0, b1)                                                      \
    asm volatile("mma.sync.aligned.m16n8k16.row.col.f32.f16.f16.f32 "          \
        "{%0,%1,%2,%3},{%4,%5,%6,%7},{%8,%9},{%0,%1,%2,%3};"                   \
        : "+f"(d[0]), "+f"(d[1]), "+f"(d[2]), "+f"(d[3])                       \
        : "r"(a[0]), "r"(a[1]), "r"(a[2]), "r"(a[3]), "r"(b0), "r"(b1))

// ============================================================================
// prep kernels (2 launches)
// ============================================================================
__global__ __launch_bounds__(256) void prep_z(const float* __restrict__ koop)
{
    __shared__ float s[64][65];
    int b = blockIdx.x;
    const float* src = koop + (size_t)b * 4096;
    for (int e = threadIdx.x; e < 4096; e += 256) {
        int l = e >> 6, i = e & 63;
        s[i][l] = src[e];
    }
    __syncthreads();
    for (int e = threadIdx.x; e < 4096; e += 256) {
        int i = e >> 6, l = e & 63;
        float v = s[i][l];
        __half h = __float2half_rn(v);
        size_t o = (size_t)(b * 64 + i) * 64 + l;
        g_zh[o] = h;
        g_zl[o] = __float2half_rn(v - __half2float(h));
    }
}

__device__ __forceinline__ void tsp_tile(const float* __restrict__ W, int K, int N,
                                         __half* __restrict__ oh)
{
    __shared__ float t[32][33];
    int tx = threadIdx.x, ty = threadIdx.y;
    int k0 = blockIdx.x * 32, n0 = blockIdx.y * 32;
#pragma unroll
    for (int j = 0; j < 4; j++)
        t[ty + j * 8][tx] = W[(size_t)(k0 + ty + j * 8) * N + n0 + tx];
    __syncthreads();
#pragma unroll
    for (int j = 0; j < 4; j++) {
        int n = n0 + ty + j * 8;
        oh[(size_t)n * K + k0 + tx] = __float2half_rn(t[tx][ty + j * 8]);
    }
}

__global__ void prep_w(const float* sW1, const float* sW2, const float* sW3,
                       const float* sW4, const float* tW1, const float* tW2,
                       const float* tW3, const float* tW4)
{
    int z = blockIdx.z;
    if (z < 4) {
        const float* W = (z == 0) ? sW2 : (z == 1) ? sW3 : (z == 2) ? tW2 : tW3;
        tsp_tile(W, 512, 512, g_w23h[z]);
    } else if (z < 6) {
        if (blockIdx.x >= 2) return;
        int mlp = z - 4;
        tsp_tile(mlp ? tW1 : sW1, 64, 512, g_w1h[mlp]);
    } else {
        int tid = threadIdx.y * 32 + threadIdx.x;
        int e = (blockIdx.y * 16 + blockIdx.x) * 256 + tid;   // 65536
        int mlp = e >> 15, rem = e & 32767;
        int i = rem >> 9, k = rem & 511;
        g_w4t[mlp][i * 512 + k] = (mlp ? tW4 : sW4)[(size_t)k * 64 + i];
    }
}

// ============================================================================
// smem layout (halves, stride 72): stage = A[128][72] | B[128][72]; x3 ring
// ============================================================================
#define ST_BYTES 36864
#define B_OFF    18432
#define G23_BIAS (3 * ST_BYTES)
#define G23_SMEM (3 * ST_BYTES + 512)
// gemm_l1: Ah @0, Al @18432, Bh @36864, bias @55296
#define L1_SMEM  55808

// ============================================================================
// gemm23: C = tanh(A @ W^T + b). 512 threads, 16 warps (4m x 4n), warp 32x32.
// 3-stage cp.async ring + register-fragment double buffering.
// grid (4 nCTA, 2048 mCTA).
// ============================================================================
__global__ __launch_bounds__(512, 2) void gemm23(
    int layer, int is_l3,
    const float* __restrict__ bias_s, const float* __restrict__ bias_t)
{
    extern __shared__ uint8_t smem[];
    const uint32_t sb = (uint32_t)__cvta_generic_to_shared(smem);
    const int tid = threadIdx.x, lane = tid & 31, wid = tid >> 5;
    const int wm = wid >> 2, wn = wid & 3;        // 4 x 4 warps
    const int grp = lane >> 2, q = lane & 3;
    const int n0 = blockIdx.x * 128;
    const int m0 = blockIdx.y * 128;
    const int mlp = (blockIdx.y >= 1024) ? 1 : 0;
    const __half* A  = layer ? g_h2 : g_h1;
    __half* O        = g_h2;                      // only used when !is_l3
    const __half* Wh = g_w23h[mlp * 2 + layer];

    if (tid < 128)
        ((float*)(smem + G23_BIAS))[tid] = (mlp ? bias_t : bias_s)[n0 + tid];

    auto load_stage = [&](uint32_t base, int k0) {
#pragma unroll
        for (int i = 0; i < 2; i++) {
            int c = tid + i * 512;
            int r = c >> 3, kc = (c & 7) << 3;
            CP16(base + (r * 72 + kc) * 2, A + (size_t)(m0 + r) * 512 + k0 + kc);
        }
#pragma unroll
        for (int i = 0; i < 2; i++) {
            int c = tid + i * 512;
            int n = c >> 3, kc = (c & 7) << 3;
            CP16(base + B_OFF + (n * 72 + kc) * 2,
                 Wh + (size_t)(n0 + n) * 512 + k0 + kc);
        }
        CP_COMMIT;
    };

    float acc[2][4][4];
#pragma unroll
    for (int a = 0; a < 2; a++)
#pragma unroll
        for (int b = 0; b < 4; b++)
#pragma unroll
            for (int c = 0; c < 4; c++) acc[a][b][c] = 0.f;

    uint32_t offA[2], offB[2];
#pragma unroll
    for (int mi = 0; mi < 2; ++mi)
        offA[mi] = ((wm * 32 + mi * 16 + (lane & 15)) * 72 + (lane >> 4) * 8) * 2;
#pragma unroll
    for (int j = 0; j < 2; ++j)
        offB[j] = B_OFF +
            ((wn * 32 + j * 16 + (lane & 7) + ((lane >> 4) << 3)) * 72 +
             ((lane >> 3) & 1) * 8) * 2;

    // register fragment double buffers
    uint32_t af[2][2][4], bfr[2][2][4];

    load_stage(sb, 0);
    load_stage(sb + ST_BYTES, 64);
#pragma unroll 1
    for (int s = 0; s < 8; ++s) {
        if (s < 7) CP_WAIT(1); else CP_WAIT(0);
        __syncthreads();
        if (s < 6) load_stage(sb + ((s + 2) % 3) * ST_BYTES, (s + 2) * 64);
        uint32_t cur = sb + (s % 3) * ST_BYTES;

        // prime ks=0 fragments
        LDSM4(af[0][0],  cur + offA[0]);
        LDSM4(af[0][1],  cur + offA[1]);
        LDSM4(bfr[0][0], cur + offB[0]);
        LDSM4(bfr[0][1], cur + offB[1]);
#pragma unroll
        for (int ks = 0; ks < 4; ++ks) {
            const int cb = ks & 1, nb = cb ^ 1;
            if (ks < 3) {               // prefetch ks+1 before consuming ks
                LDSM4(af[nb][0],  cur + offA[0] + (ks + 1) * 32);
                LDSM4(af[nb][1],  cur + offA[1] + (ks + 1) * 32);
                LDSM4(bfr[nb][0], cur + offB[0] + (ks + 1) * 32);
                LDSM4(bfr[nb][1], cur + offB[1] + (ks + 1) * 32);
            }
            MMA(acc[0][0], af[cb][0], bfr[cb][0][0], bfr[cb][0][1]);
            MMA(acc[0][1], af[cb][0], bfr[cb][0][2], bfr[cb][0][3]);
            MMA(acc[1][0], af[cb][1], bfr[cb][0][0], bfr[cb][0][1]);
            MMA(acc[1][1], af[cb][1], bfr[cb][0][2], bfr[cb][0][3]);
            MMA(acc[0][2], af[cb][0], bfr[cb][1][0], bfr[cb][1][1]);
            MMA(acc[0][3], af[cb][0], bfr[cb][1][2], bfr[cb][1][3]);
            MMA(acc[1][2], af[cb][1], bfr[cb][1][0], bfr[cb][1][1]);
            MMA(acc[1][3], af[cb][1], bfr[cb][1][2], bfr[cb][1][3]);
        }
    }
    __syncthreads();

    const float* sbias = (const float*)(smem + G23_BIAS);
    if (!is_l3) {
#pragma unroll
        for (int mi = 0; mi < 2; ++mi)
#pragma unroll
        for (int nj = 0; nj < 4; ++nj) {
            int row = m0 + wm * 32 + mi * 16 + grp;
            int cl  = wn * 32 + nj * 8 + q * 2;
            float b0 = sbias[cl], b1 = sbias[cl + 1];
            float v00 = tanhf(acc[mi][nj][0] + b0);
            float v01 = tanhf(acc[mi][nj][1] + b1);
            float v10 = tanhf(acc[mi][nj][2] + b0);
            float v11 = tanhf(acc[mi][nj][3] + b1);
            size_t o0 = (size_t)row * 512 + n0 + cl;
            *reinterpret_cast<__half2*>(O + o0) =
                __halves2half2(__float2half_rn(v00), __float2half_rn(v01));
            *reinterpret_cast<__half2*>(O + o0 + 8 * 512) =
                __halves2half2(__float2half_rn(v10), __float2half_rn(v11));
        }
    } else {
        // stage W4^T slice [64 i][128 n] fp32 into dead ring area
        float* sw4 = (float*)smem;
        for (int e = tid; e < 8192; e += 512) {
            int i = e >> 7, c = e & 127;
            sw4[i * 129 + c] = g_w4t[mlp][i * 512 + n0 + c];
        }
        __syncthreads();
        const int iA = (wm * 32 + grp) & 63;
        float ps[2][2];
        ps[0][0] = ps[0][1] = ps[1][0] = ps[1][1] = 0.f;
#pragma unroll
        for (int mi = 0; mi < 2; ++mi)
#pragma unroll
        for (int nj = 0; nj < 4; ++nj) {
            int cl = wn * 32 + nj * 8 + q * 2;
            float b0 = sbias[cl], b1 = sbias[cl + 1];
            int i0 = (iA + mi * 16) & 63, i1 = (iA + mi * 16 + 8) & 63;
            ps[mi][0] += tanhf(acc[mi][nj][0] + b0) * sw4[i0 * 129 + cl]
                       + tanhf(acc[mi][nj][1] + b1) * sw4[i0 * 129 + cl + 1];
            ps[mi][1] += tanhf(acc[mi][nj][2] + b0) * sw4[i1 * 129 + cl]
                       + tanhf(acc[mi][nj][3] + b1) * sw4[i1 * 129 + cl + 1];
        }
        int slice = blockIdx.x * 4 + wn;
#pragma unroll
        for (int mi = 0; mi < 2; ++mi)
#pragma unroll
        for (int rh = 0; rh < 2; ++rh) {
            float v = ps[mi][rh];
            v += __shfl_xor_sync(0xffffffffu, v, 1);
            v += __shfl_xor_sync(0xffffffffu, v, 2);
            if (q == 0)
                g_part[slice][m0 + wm * 32 + mi * 16 + rh * 8 + grp] = v;
        }
    }
}

// ============================================================================
// gemm_l1: K=64, Z split (Zh+Zl, 2 products), W1 fp16. grid (4, 2048).
// ============================================================================
__global__ __launch_bounds__(256, 2) void gemm_l1(
    const float* __restrict__ b1s, const float* __restrict__ b1t)
{
    extern __shared__ uint8_t smem[];
    const uint32_t sb = (uint32_t)__cvta_generic_to_shared(smem);
    const int tid = threadIdx.x, lane = tid & 31, wid = tid >> 5;
    const int wm = wid >> 2, wn = wid & 3;
    const int grp = lane >> 2, q = lane & 3;
    const int n0 = blockIdx.x * 128;
    const int mlp = (blockIdx.y >= 1024) ? 1 : 0;
    const int zrow0 = (blockIdx.y & 1023) * 128;
    const int m0 = blockIdx.y * 128;

    if (tid < 128)
        ((float*)(smem + 55296))[tid] = (mlp ? b1t : b1s)[n0 + tid];

#pragma unroll
    for (int i = 0; i < 8; i++) {
        int c = tid + i * 256;
        int hl = c >> 10, cc = c & 1023;
        int r = cc >> 3, kc = (cc & 7) << 3;
        const __half* src = (hl ? g_zl : g_zh) + (size_t)(zrow0 + r) * 64 + kc;
        CP16(sb + hl * 18432 + (r * 72 + kc) * 2, src);
    }
#pragma unroll
    for (int i = 0; i < 4; i++) {
        int c = tid + i * 256;
        int n = c >> 3, kc = (c & 7) << 3;
        CP16(sb + 36864 + (n * 72 + kc) * 2,
             g_w1h[mlp] + (size_t)(n0 + n) * 64 + kc);
    }
    CP_COMMIT; CP_WAIT(0);
    __syncthreads();

    float acc[4][4][4];
#pragma unroll
    for (int a = 0; a < 4; a++)
#pragma unroll
        for (int b = 0; b < 4; b++)
#pragma unroll
            for (int c = 0; c < 4; c++) acc[a][b][c] = 0.f;

    uint32_t offA[4], offB[2];
#pragma unroll
    for (int mi = 0; mi < 4; ++mi)
        offA[mi] = ((wm * 64 + mi * 16 + (lane & 15)) * 72 + (lane >> 4) * 8) * 2;
#pragma unroll
    for (int j = 0; j < 2; ++j)
        offB[j] = 36864 +
            ((wn * 32 + j * 16 + (lane & 7) + ((lane >> 4) << 3)) * 72 +
             ((lane >> 3) & 1) * 8) * 2;

#pragma unroll
    for (int ks = 0; ks < 64; ks += 16) {
        uint32_t ah[4][4], al[4][4];
#pragma unroll
        for (int mi = 0; mi < 4; ++mi) {
            LDSM4(ah[mi], sb + offA[mi] + ks * 2);
            LDSM4(al[mi], sb + 18432 + offA[mi] + ks * 2);
        }
#pragma unroll
        for (int j = 0; j < 2; ++j) {
            uint32_t b[4];
            LDSM4(b, sb + offB[j] + ks * 2);
#pragma unroll
            for (int mi = 0; mi < 4; ++mi) {
                MMA(acc[mi][j * 2],     ah[mi], b[0], b[1]);
                MMA(acc[mi][j * 2],     al[mi], b[0], b[1]);
                MMA(acc[mi][j * 2 + 1], ah[mi], b[2], b[3]);
                MMA(acc[mi][j * 2 + 1], al[mi], b[2], b[3]);
            }
        }
    }

    const float* sbias = (const float*)(smem + 55296);
#pragma unroll
    for (int mi = 0; mi < 4; ++mi)
#pragma unroll
    for (int nj = 0; nj < 4; ++nj) {
        int row = m0 + wm * 64 + mi * 16 + grp;
        int cl  = wn * 32 + nj * 8 + q * 2;
        float b0 = sbias[cl], b1 = sbias[cl + 1];
        float v00 = tanhf(acc[mi][nj][0] + b0);
        float v01 = tanhf(acc[mi][nj][1] + b1);
        float v10 = tanhf(acc[mi][nj][2] + b0);
        float v11 = tanhf(acc[mi][nj][3] + b1);
        size_t o0 = (size_t)row * 512 + n0 + cl;
        *reinterpret_cast<__half2*>(g_h1 + o0) =
            __halves2half2(__float2half_rn(v00), __float2half_rn(v01));
        *reinterpret_cast<__half2*>(g_h1 + o0 + 8 * 512) =
            __halves2half2(__float2half_rn(v10), __float2half_rn(v11));
    }
}

// ============================================================================
__global__ __launch_bounds__(256) void final_k(
    const float* __restrict__ x, const float* __restrict__ sb4,
    const float* __restrict__ tb4, float* __restrict__ out)
{
    int r = blockIdx.x * 256 + threadIdx.x;
    int i = r & 63;
    float ds = sb4[i], dt = tb4[i];
#pragma unroll
    for (int s = 0; s < 16; s++) {
        ds += g_part[s][r];
        dt += g_part[s][HALF_M + r];
    }
    out[r] = (x[r] - dt) * expf(-ds);
}

// ============================================================================
extern "C" void kernel_launch(void* const* d_in, const int* in_sizes, int n_in,
                              void* d_out, int out_size)
{
    (void)in_sizes; (void)n_in; (void)out_size;
    const float* x    = (const float*)d_in[0];
    const float* koop = (const float*)d_in[1];
    const float* sW1 = (const float*)d_in[2];  const float* sb1 = (const float*)d_in[3];
    const float* sW2 = (const float*)d_in[4];  const float* sb2 = (const float*)d_in[5];
    const float* sW3 = (const float*)d_in[6];  const float* sb3 = (const float*)d_in[7];
    const float* sW4 = (const float*)d_in[8];  const float* sb4 = (const float*)d_in[9];
    const float* tW1 = (const float*)d_in[10]; const float* tb1 = (const float*)d_in[11];
    const float* tW2 = (const float*)d_in[12]; const float* tb2 = (const float*)d_in[13];
    const float* tW3 = (const float*)d_in[14]; const float* tb3 = (const float*)d_in[15];
    const float* tW4 = (const float*)d_in[16]; const float* tb4 = (const float*)d_in[17];
    float* out = (float*)d_out;

    static int done = 0;
    if (!done) {
        cudaFuncSetAttribute(gemm23, cudaFuncAttributeMaxDynamicSharedMemorySize, G23_SMEM);
        cudaFuncSetAttribute(gemm_l1, cudaFuncAttributeMaxDynamicSharedMemorySize, L1_SMEM);
        done = 1;
    }

    prep_z<<<2048, 256>>>(koop);
    prep_w<<<dim3(16, 16, 7), dim3(32, 8)>>>(sW1, sW2, sW3, sW4,
                                             tW1, tW2, tW3, tW4);

    dim3 grid(4, 2048);
    gemm_l1<<<grid, 256, L1_SMEM>>>(sb1, tb1);
    gemm23 <<<grid, 512, G23_SMEM>>>(0, 0, sb2, tb2);
    gemm23 <<<grid, 512, G23_SMEM>>>(1, 1, sb3, tb3);
    final_k<<<512, 256>>>(x, sb4, tb4, out);
}

// round 14
// speedup vs baseline: 1.0393x; 1.0285x over previous
#include <cuda_runtime.h>
#include <cuda_fp16.h>
#include <math.h>
#include <stdint.h>

// ============================================================================
// Decoder_33208687133135 — Round 14: gemm_l1 down to 1 product (Z plain fp16),
// prep_z simplified. gemm23 kept at the measured HMMA ceiling (~457us/launch).
// rows r (per MLP, 131072): Z[r][l] = koopman[r>>6][l][r&63]
// h1=tanh(Z W1+b1); h2=tanh(h1 W2+b2); h3=tanh(h2 W3+b3); diag=h3.W4[:,r&63]
// out = (x - dt) * exp(-ds)
// ============================================================================

#define HALF_M 131072
#define MTOT   262144

// ---- static scratch --------------------------------------------------------
__device__ __half g_z[(size_t)HALF_M * 64];      // Z fp16
__device__ __half g_w1h[2][512 * 64];            // [mlp], W1^T [n][k] fp16
__device__ __half g_w23h[4][512 * 512];          // [mlp*2+layer], W^T [n][k] fp16
__device__ float  g_w4t[2][64 * 512];            // [mlp], W4^T [i][k]
__device__ __half g_h1[(size_t)MTOT * 512];
__device__ __half g_h2[(size_t)MTOT * 512];
__device__ float  g_part[16][MTOT];              // diag partials per 32-n slice

// ---- PTX helpers -----------------------------------------------------------
#define CP16(d, s) asm volatile("cp.async.cg.shared.global [%0], [%1], 16;" :: "r"(d), "l"(s))
#define CP_COMMIT  asm volatile("cp.async.commit_group;")
#define CP_WAIT(n) asm volatile("cp.async.wait_group %0;" :: "n"(n) : "memory")

#define LDSM4(R, addr)                                                         \
    asm volatile("ldmatrix.sync.aligned.m8n8.x4.shared.b16 {%0,%1,%2,%3}, [%4];" \
        : "=r"(R[0]), "=r"(R[1]), "=r"(R[2]), "=r"(R[3]) : "r"(addr))

#define MMA(d, a, b0, b1)                                                      \
    asm volatile("mma.sync.aligned.m16n8k16.row.col.f32.f16.f16.f32 "          \
        "{%0,%1,%2,%3},{%4,%5,%6,%7},{%8,%9},{%0,%1,%2,%3};"                   \
        : "+f"(d[0]), "+f"(d[1]), "+f"(d[2]), "+f"(d[3])                       \
        : "r"(a[0]), "r"(a[1]), "r"(a[2]), "r"(a[3]), "r"(b0), "r"(b1))

// ============================================================================
// prep kernels (2 launches)
// ============================================================================
__global__ __launch_bounds__(256) void prep_z(const float* __restrict__ koop)
{
    __shared__ float s[64][65];
    int b = blockIdx.x;
    const float* src = koop + (size_t)b * 4096;
    for (int e = threadIdx.x; e < 4096; e += 256) {
        int l = e >> 6, i = e & 63;
        s[i][l] = src[e];
    }
    __syncthreads();
    for (int e = threadIdx.x; e < 4096; e += 256) {
        int i = e >> 6, l = e & 63;
        g_z[(size_t)(b * 64 + i) * 64 + l] = __float2half_rn(s[i][l]);
    }
}

__device__ __forceinline__ void tsp_tile(const float* __restrict__ W, int K, int N,
                                         __half* __restrict__ oh)
{
    __shared__ float t[32][33];
    int tx = threadIdx.x, ty = threadIdx.y;
    int k0 = blockIdx.x * 32, n0 = blockIdx.y * 32;
#pragma unroll
    for (int j = 0; j < 4; j++)
        t[ty + j * 8][tx] = W[(size_t)(k0 + ty + j * 8) * N + n0 + tx];
    __syncthreads();
#pragma unroll
    for (int j = 0; j < 4; j++) {
        int n = n0 + ty + j * 8;
        oh[(size_t)n * K + k0 + tx] = __float2half_rn(t[tx][ty + j * 8]);
    }
}

__global__ void prep_w(const float* sW1, const float* sW2, const float* sW3,
                       const float* sW4, const float* tW1, const float* tW2,
                       const float* tW3, const float* tW4)
{
    int z = blockIdx.z;
    if (z < 4) {
        const float* W = (z == 0) ? sW2 : (z == 1) ? sW3 : (z == 2) ? tW2 : tW3;
        tsp_tile(W, 512, 512, g_w23h[z]);
    } else if (z < 6) {
        if (blockIdx.x >= 2) return;
        int mlp = z - 4;
        tsp_tile(mlp ? tW1 : sW1, 64, 512, g_w1h[mlp]);
    } else {
        int tid = threadIdx.y * 32 + threadIdx.x;
        int e = (blockIdx.y * 16 + blockIdx.x) * 256 + tid;   // 65536
        int mlp = e >> 15, rem = e & 32767;
        int i = rem >> 9, k = rem & 511;
        g_w4t[mlp][i * 512 + k] = (mlp ? tW4 : sW4)[(size_t)k * 64 + i];
    }
}

// ============================================================================
// smem layout (halves, stride 72): stage = A[128][72] | B[128][72]; x3 ring
// ============================================================================
#define ST_BYTES 36864
#define B_OFF    18432
#define G23_BIAS (3 * ST_BYTES)
#define G23_SMEM (3 * ST_BYTES + 512)
// gemm_l1: A @0, B @18432, bias @36864
#define L1_SMEM  37376

// ============================================================================
// gemm23: C = tanh(A @ W^T + b). 512 threads, 16 warps (4m x 4n), warp 32x32.
// 3-stage cp.async ring + register-fragment double buffering (R13 measured
// best; sits on the ~50% HMMA ceiling). grid (4 nCTA, 2048 mCTA).
// ============================================================================
__global__ __launch_bounds__(512, 2) void gemm23(
    int layer, int is_l3,
    const float* __restrict__ bias_s, const float* __restrict__ bias_t)
{
    extern __shared__ uint8_t smem[];
    const uint32_t sb = (uint32_t)__cvta_generic_to_shared(smem);
    const int tid = threadIdx.x, lane = tid & 31, wid = tid >> 5;
    const int wm = wid >> 2, wn = wid & 3;        // 4 x 4 warps
    const int grp = lane >> 2, q = lane & 3;
    const int n0 = blockIdx.x * 128;
    const int m0 = blockIdx.y * 128;
    const int mlp = (blockIdx.y >= 1024) ? 1 : 0;
    const __half* A  = layer ? g_h2 : g_h1;
    __half* O        = g_h2;                      // only used when !is_l3
    const __half* Wh = g_w23h[mlp * 2 + layer];

    if (tid < 128)
        ((float*)(smem + G23_BIAS))[tid] = (mlp ? bias_t : bias_s)[n0 + tid];

    auto load_stage = [&](uint32_t base, int k0) {
#pragma unroll
        for (int i = 0; i < 2; i++) {
            int c = tid + i * 512;
            int r = c >> 3, kc = (c & 7) << 3;
            CP16(base + (r * 72 + kc) * 2, A + (size_t)(m0 + r) * 512 + k0 + kc);
        }
#pragma unroll
        for (int i = 0; i < 2; i++) {
            int c = tid + i * 512;
            int n = c >> 3, kc = (c & 7) << 3;
            CP16(base + B_OFF + (n * 72 + kc) * 2,
                 Wh + (size_t)(n0 + n) * 512 + k0 + kc);
        }
        CP_COMMIT;
    };

    float acc[2][4][4];
#pragma unroll
    for (int a = 0; a < 2; a++)
#pragma unroll
        for (int b = 0; b < 4; b++)
#pragma unroll
            for (int c = 0; c < 4; c++) acc[a][b][c] = 0.f;

    uint32_t offA[2], offB[2];
#pragma unroll
    for (int mi = 0; mi < 2; ++mi)
        offA[mi] = ((wm * 32 + mi * 16 + (lane & 15)) * 72 + (lane >> 4) * 8) * 2;
#pragma unroll
    for (int j = 0; j < 2; ++j)
        offB[j] = B_OFF +
            ((wn * 32 + j * 16 + (lane & 7) + ((lane >> 4) << 3)) * 72 +
             ((lane >> 3) & 1) * 8) * 2;

    uint32_t af[2][2][4], bfr[2][2][4];

    load_stage(sb, 0);
    load_stage(sb + ST_BYTES, 64);
#pragma unroll 1
    for (int s = 0; s < 8; ++s) {
        if (s < 7) CP_WAIT(1); else CP_WAIT(0);
        __syncthreads();
        if (s < 6) load_stage(sb + ((s + 2) % 3) * ST_BYTES, (s + 2) * 64);
        uint32_t cur = sb + (s % 3) * ST_BYTES;

        LDSM4(af[0][0],  cur + offA[0]);
        LDSM4(af[0][1],  cur + offA[1]);
        LDSM4(bfr[0][0], cur + offB[0]);
        LDSM4(bfr[0][1], cur + offB[1]);
#pragma unroll
        for (int ks = 0; ks < 4; ++ks) {
            const int cb = ks & 1, nb = cb ^ 1;
            if (ks < 3) {
                LDSM4(af[nb][0],  cur + offA[0] + (ks + 1) * 32);
                LDSM4(af[nb][1],  cur + offA[1] + (ks + 1) * 32);
                LDSM4(bfr[nb][0], cur + offB[0] + (ks + 1) * 32);
                LDSM4(bfr[nb][1], cur + offB[1] + (ks + 1) * 32);
            }
            MMA(acc[0][0], af[cb][0], bfr[cb][0][0], bfr[cb][0][1]);
            MMA(acc[0][1], af[cb][0], bfr[cb][0][2], bfr[cb][0][3]);
            MMA(acc[1][0], af[cb][1], bfr[cb][0][0], bfr[cb][0][1]);
            MMA(acc[1][1], af[cb][1], bfr[cb][0][2], bfr[cb][0][3]);
            MMA(acc[0][2], af[cb][0], bfr[cb][1][0], bfr[cb][1][1]);
            MMA(acc[0][3], af[cb][0], bfr[cb][1][2], bfr[cb][1][3]);
            MMA(acc[1][2], af[cb][1], bfr[cb][1][0], bfr[cb][1][1]);
            MMA(acc[1][3], af[cb][1], bfr[cb][1][2], bfr[cb][1][3]);
        }
    }
    __syncthreads();

    const float* sbias = (const float*)(smem + G23_BIAS);
    if (!is_l3) {
#pragma unroll
        for (int mi = 0; mi < 2; ++mi)
#pragma unroll
        for (int nj = 0; nj < 4; ++nj) {
            int row = m0 + wm * 32 + mi * 16 + grp;
            int cl  = wn * 32 + nj * 8 + q * 2;
            float b0 = sbias[cl], b1 = sbias[cl + 1];
            float v00 = tanhf(acc[mi][nj][0] + b0);
            float v01 = tanhf(acc[mi][nj][1] + b1);
            float v10 = tanhf(acc[mi][nj][2] + b0);
            float v11 = tanhf(acc[mi][nj][3] + b1);
            size_t o0 = (size_t)row * 512 + n0 + cl;
            *reinterpret_cast<__half2*>(O + o0) =
                __halves2half2(__float2half_rn(v00), __float2half_rn(v01));
            *reinterpret_cast<__half2*>(O + o0 + 8 * 512) =
                __halves2half2(__float2half_rn(v10), __float2half_rn(v11));
        }
    } else {
        // stage W4^T slice [64 i][128 n] fp32 into dead ring area
        float* sw4 = (float*)smem;
        for (int e = tid; e < 8192; e += 512) {
            int i = e >> 7, c = e & 127;
            sw4[i * 129 + c] = g_w4t[mlp][i * 512 + n0 + c];
        }
        __syncthreads();
        const int iA = (wm * 32 + grp) & 63;
        float ps[2][2];
        ps[0][0] = ps[0][1] = ps[1][0] = ps[1][1] = 0.f;
#pragma unroll
        for (int mi = 0; mi < 2; ++mi)
#pragma unroll
        for (int nj = 0; nj < 4; ++nj) {
            int cl = wn * 32 + nj * 8 + q * 2;
            float b0 = sbias[cl], b1 = sbias[cl + 1];
            int i0 = (iA + mi * 16) & 63, i1 = (iA + mi * 16 + 8) & 63;
            ps[mi][0] += tanhf(acc[mi][nj][0] + b0) * sw4[i0 * 129 + cl]
                       + tanhf(acc[mi][nj][1] + b1) * sw4[i0 * 129 + cl + 1];
            ps[mi][1] += tanhf(acc[mi][nj][2] + b0) * sw4[i1 * 129 + cl]
                       + tanhf(acc[mi][nj][3] + b1) * sw4[i1 * 129 + cl + 1];
        }
        int slice = blockIdx.x * 4 + wn;
#pragma unroll
        for (int mi = 0; mi < 2; ++mi)
#pragma unroll
        for (int rh = 0; rh < 2; ++rh) {
            float v = ps[mi][rh];
            v += __shfl_xor_sync(0xffffffffu, v, 1);
            v += __shfl_xor_sync(0xffffffffu, v, 2);
            if (q == 0)
                g_part[slice][m0 + wm * 32 + mi * 16 + rh * 8 + grp] = v;
        }
    }
}

// ============================================================================
// gemm_l1: K=64, Z fp16, W1 fp16, 1 product. grid (4, 2048), 256 threads,
// warp tile 64x32.
// ============================================================================
__global__ __launch_bounds__(256, 2) void gemm_l1(
    const float* __restrict__ b1s, const float* __restrict__ b1t)
{
    extern __shared__ uint8_t smem[];
    const uint32_t sb = (uint32_t)__cvta_generic_to_shared(smem);
    const int tid = threadIdx.x, lane = tid & 31, wid = tid >> 5;
    const int wm = wid >> 2, wn = wid & 3;
    const int grp = lane >> 2, q = lane & 3;
    const int n0 = blockIdx.x * 128;
    const int mlp = (blockIdx.y >= 1024) ? 1 : 0;
    const int zrow0 = (blockIdx.y & 1023) * 128;
    const int m0 = blockIdx.y * 128;

    if (tid < 128)
        ((float*)(smem + 36864))[tid] = (mlp ? b1t : b1s)[n0 + tid];

    // A: Z 128x64 @0 ; B: W1^T 128x64 @18432
#pragma unroll
    for (int i = 0; i < 4; i++) {
        int c = tid + i * 256;
        int r = c >> 3, kc = (c & 7) << 3;
        CP16(sb + (r * 72 + kc) * 2, g_z + (size_t)(zrow0 + r) * 64 + kc);
    }
#pragma unroll
    for (int i = 0; i < 4; i++) {
        int c = tid + i * 256;
        int n = c >> 3, kc = (c & 7) << 3;
        CP16(sb + 18432 + (n * 72 + kc) * 2,
             g_w1h[mlp] + (size_t)(n0 + n) * 64 + kc);
    }
    CP_COMMIT; CP_WAIT(0);
    __syncthreads();

    float acc[4][4][4];
#pragma unroll
    for (int a = 0; a < 4; a++)
#pragma unroll
        for (int b = 0; b < 4; b++)
#pragma unroll
            for (int c = 0; c < 4; c++) acc[a][b][c] = 0.f;

    uint32_t offA[4], offB[2];
#pragma unroll
    for (int mi = 0; mi < 4; ++mi)
        offA[mi] = ((wm * 64 + mi * 16 + (lane & 15)) * 72 + (lane >> 4) * 8) * 2;
#pragma unroll
    for (int j = 0; j < 2; ++j)
        offB[j] = 18432 +
            ((wn * 32 + j * 16 + (lane & 7) + ((lane >> 4) << 3)) * 72 +
             ((lane >> 3) & 1) * 8) * 2;

#pragma unroll
    for (int ks = 0; ks < 64; ks += 16) {
        uint32_t a[4][4];
#pragma unroll
        for (int mi = 0; mi < 4; ++mi) LDSM4(a[mi], sb + offA[mi] + ks * 2);
#pragma unroll
        for (int j = 0; j < 2; ++j) {
            uint32_t b[4];
            LDSM4(b, sb + offB[j] + ks * 2);
#pragma unroll
            for (int mi = 0; mi < 4; ++mi) {
                MMA(acc[mi][j * 2],     a[mi], b[0], b[1]);
                MMA(acc[mi][j * 2 + 1], a[mi], b[2], b[3]);
            }
        }
    }

    const float* sbias = (const float*)(smem + 36864);
#pragma unroll
    for (int mi = 0; mi < 4; ++mi)
#pragma unroll
    for (int nj = 0; nj < 4; ++nj) {
        int row = m0 + wm * 64 + mi * 16 + grp;
        int cl  = wn * 32 + nj * 8 + q * 2;
        float b0 = sbias[cl], b1 = sbias[cl + 1];
        float v00 = tanhf(acc[mi][nj][0] + b0);
        float v01 = tanhf(acc[mi][nj][1] + b1);
        float v10 = tanhf(acc[mi][nj][2] + b0);
        float v11 = tanhf(acc[mi][nj][3] + b1);
        size_t o0 = (size_t)row * 512 + n0 + cl;
        *reinterpret_cast<__half2*>(g_h1 + o0) =
            __halves2half2(__float2half_rn(v00), __float2half_rn(v01));
        *reinterpret_cast<__half2*>(g_h1 + o0 + 8 * 512) =
            __halves2half2(__float2half_rn(v10), __float2half_rn(v11));
    }
}

// ============================================================================
__global__ __launch_bounds__(256) void final_k(
    const float* __restrict__ x, const float* __restrict__ sb4,
    const float* __restrict__ tb4, float* __restrict__ out)
{
    int r = blockIdx.x * 256 + threadIdx.x;
    int i = r & 63;
    float ds = sb4[i], dt = tb4[i];
#pragma unroll
    for (int s = 0; s < 16; s++) {
        ds += g_part[s][r];
        dt += g_part[s][HALF_M + r];
    }
    out[r] = (x[r] - dt) * expf(-ds);
}

// ============================================================================
extern "C" void kernel_launch(void* const* d_in, const int* in_sizes, int n_in,
                              void* d_out, int out_size)
{
    (void)in_sizes; (void)n_in; (void)out_size;
    const float* x    = (const float*)d_in[0];
    const float* koop = (const float*)d_in[1];
    const float* sW1 = (const float*)d_in[2];  const float* sb1 = (const float*)d_in[3];
    const float* sW2 = (const float*)d_in[4];  const float* sb2 = (const float*)d_in[5];
    const float* sW3 = (const float*)d_in[6];  const float* sb3 = (const float*)d_in[7];
    const float* sW4 = (const float*)d_in[8];  const float* sb4 = (const float*)d_in[9];
    const float* tW1 = (const float*)d_in[10]; const float* tb1 = (const float*)d_in[11];
    const float* tW2 = (const float*)d_in[12]; const float* tb2 = (const float*)d_in[13];
    const float* tW3 = (const float*)d_in[14]; const float* tb3 = (const float*)d_in[15];
    const float* tW4 = (const float*)d_in[16]; const float* tb4 = (const float*)d_in[17];
    float* out = (float*)d_out;

    static int done = 0;
    if (!done) {
        cudaFuncSetAttribute(gemm23, cudaFuncAttributeMaxDynamicSharedMemorySize, G23_SMEM);
        cudaFuncSetAttribute(gemm_l1, cudaFuncAttributeMaxDynamicSharedMemorySize, L1_SMEM);
        done = 1;
    }

    prep_z<<<2048, 256>>>(koop);
    prep_w<<<dim3(16, 16, 7), dim3(32, 8)>>>(sW1, sW2, sW3, sW4,
                                             tW1, tW2, tW3, tW4);

    dim3 grid(4, 2048);
    gemm_l1<<<grid, 256, L1_SMEM>>>(sb1, tb1);
    gemm23 <<<grid, 512, G23_SMEM>>>(0, 0, sb2, tb2);
    gemm23 <<<grid, 512, G23_SMEM>>>(1, 1, sb3, tb3);
    final_k<<<512, 256>>>(x, sb4, tb4, out);
}

// round 16
// speedup vs baseline: 1.0491x; 1.0094x over previous
#include <cuda_runtime.h>
#include <cuda_fp16.h>
#include <math.h>
#include <stdint.h>

// ============================================================================
// Decoder_33208687133135 — Round 15: gemm_l1 pipelined over 4 m-tiles/CTA
// (B loaded once, 2-stage A ring). gemm23 kept at measured HMMA ceiling.
// rows r (per MLP, 131072): Z[r][l] = koopman[r>>6][l][r&63]
// h1=tanh(Z W1+b1); h2=tanh(h1 W2+b2); h3=tanh(h2 W3+b3); diag=h3.W4[:,r&63]
// out = (x - dt) * exp(-ds)
// ============================================================================

#define HALF_M 131072
#define MTOT   262144

// ---- static scratch --------------------------------------------------------
__device__ __half g_z[(size_t)HALF_M * 64];      // Z fp16
__device__ __half g_w1h[2][512 * 64];            // [mlp], W1^T [n][k] fp16
__device__ __half g_w23h[4][512 * 512];          // [mlp*2+layer], W^T [n][k] fp16
__device__ float  g_w4t[2][64 * 512];            // [mlp], W4^T [i][k]
__device__ __half g_h1[(size_t)MTOT * 512];
__device__ __half g_h2[(size_t)MTOT * 512];
__device__ float  g_part[16][MTOT];              // diag partials per 32-n slice

// ---- PTX helpers -----------------------------------------------------------
#define CP16(d, s) asm volatile("cp.async.cg.shared.global [%0], [%1], 16;" :: "r"(d), "l"(s))
#define CP_COMMIT  asm volatile("cp.async.commit_group;")
#define CP_WAIT(n) asm volatile("cp.async.wait_group %0;" :: "n"(n) : "memory")

#define LDSM4(R, addr)                                                         \
    asm volatile("ldmatrix.sync.aligned.m8n8.x4.shared.b16 {%0,%1,%2,%3}, [%4];" \
        : "=r"(R[0]), "=r"(R[1]), "=r"(R[2]), "=r"(R[3]) : "r"(addr))

#define MMA(d, a, b0, b1)                                                      \
    asm volatile("mma.sync.aligned.m16n8k16.row.col.f32.f16.f16.f32 "          \
        "{%0,%1,%2,%3},{%4,%5,%6,%7},{%8,%9},{%0,%1,%2,%3};"                   \
        : "+f"(d[0]), "+f"(d[1]), "+f"(d[2]), "+f"(d[3])                       \
        : "r"(a[0]), "r"(a[1]), "r"(a[2]), "r"(a[3]), "r"(b0), "r"(b1))

// ============================================================================
// prep kernels (2 launches)
// ============================================================================
__global__ __launch_bounds__(256) void prep_z(const float* __restrict__ koop)
{
    __shared__ float s[64][65];
    int b = blockIdx.x;
    const float* src = koop + (size_t)b * 4096;
    for (int e = threadIdx.x; e < 4096; e += 256) {
        int l = e >> 6, i = e & 63;
        s[i][l] = src[e];
    }
    __syncthreads();
    for (int e = threadIdx.x; e < 4096; e += 256) {
        int i = e >> 6, l = e & 63;
        g_z[(size_t)(b * 64 + i) * 64 + l] = __float2half_rn(s[i][l]);
    }
}

__device__ __forceinline__ void tsp_tile(const float* __restrict__ W, int K, int N,
                                         __half* __restrict__ oh)
{
    __shared__ float t[32][33];
    int tx = threadIdx.x, ty = threadIdx.y;
    int k0 = blockIdx.x * 32, n0 = blockIdx.y * 32;
#pragma unroll
    for (int j = 0; j < 4; j++)
        t[ty + j * 8][tx] = W[(size_t)(k0 + ty + j * 8) * N + n0 + tx];
    __syncthreads();
#pragma unroll
    for (int j = 0; j < 4; j++) {
        int n = n0 + ty + j * 8;
        oh[(size_t)n * K + k0 + tx] = __float2half_rn(t[tx][ty + j * 8]);
    }
}

__global__ void prep_w(const float* sW1, const float* sW2, const float* sW3,
                       const float* sW4, const float* tW1, const float* tW2,
                       const float* tW3, const float* tW4)
{
    int z = blockIdx.z;
    if (z < 4) {
        const float* W = (z == 0) ? sW2 : (z == 1) ? sW3 : (z == 2) ? tW2 : tW3;
        tsp_tile(W, 512, 512, g_w23h[z]);
    } else if (z < 6) {
        if (blockIdx.x >= 2) return;
        int mlp = z - 4;
        tsp_tile(mlp ? tW1 : sW1, 64, 512, g_w1h[mlp]);
    } else {
        int tid = threadIdx.y * 32 + threadIdx.x;
        int e = (blockIdx.y * 16 + blockIdx.x) * 256 + tid;   // 65536
        int mlp = e >> 15, rem = e & 32767;
        int i = rem >> 9, k = rem & 511;
        g_w4t[mlp][i * 512 + k] = (mlp ? tW4 : sW4)[(size_t)k * 64 + i];
    }
}

// ============================================================================
// smem layouts (halves, stride 72)
// ============================================================================
#define ST_BYTES 36864
#define B_OFF    18432
#define G23_BIAS (3 * ST_BYTES)
#define G23_SMEM (3 * ST_BYTES + 512)
// gemm_l1: B @0 (18432), A ring @18432 x2, bias @55296
#define L1A_OFF  18432
#define L1_BIAS  55296
#define L1_SMEM  55808

// ============================================================================
// gemm23: C = tanh(A @ W^T + b). 512 threads, 16 warps (4m x 4n), warp 32x32.
// 3-stage cp.async ring + register-fragment double buffering (measured best;
// sits on the ~50% HMMA ceiling). grid (4 nCTA, 2048 mCTA).
// ============================================================================
__global__ __launch_bounds__(512, 2) void gemm23(
    int layer, int is_l3,
    const float* __restrict__ bias_s, const float* __restrict__ bias_t)
{
    extern __shared__ uint8_t smem[];
    const uint32_t sb = (uint32_t)__cvta_generic_to_shared(smem);
    const int tid = threadIdx.x, lane = tid & 31, wid = tid >> 5;
    const int wm = wid >> 2, wn = wid & 3;        // 4 x 4 warps
    const int grp = lane >> 2, q = lane & 3;
    const int n0 = blockIdx.x * 128;
    const int m0 = blockIdx.y * 128;
    const int mlp = (blockIdx.y >= 1024) ? 1 : 0;
    const __half* A  = layer ? g_h2 : g_h1;
    __half* O        = g_h2;                      // only used when !is_l3
    const __half* Wh = g_w23h[mlp * 2 + layer];

    if (tid < 128)
        ((float*)(smem + G23_BIAS))[tid] = (mlp ? bias_t : bias_s)[n0 + tid];

    auto load_stage = [&](uint32_t base, int k0) {
#pragma unroll
        for (int i = 0; i < 2; i++) {
            int c = tid + i * 512;
            int r = c >> 3, kc = (c & 7) << 3;
            CP16(base + (r * 72 + kc) * 2, A + (size_t)(m0 + r) * 512 + k0 + kc);
        }
#pragma unroll
        for (int i = 0; i < 2; i++) {
            int c = tid + i * 512;
            int n = c >> 3, kc = (c & 7) << 3;
            CP16(base + B_OFF + (n * 72 + kc) * 2,
                 Wh + (size_t)(n0 + n) * 512 + k0 + kc);
        }
        CP_COMMIT;
    };

    float acc[2][4][4];
#pragma unroll
    for (int a = 0; a < 2; a++)
#pragma unroll
        for (int b = 0; b < 4; b++)
#pragma unroll
            for (int c = 0; c < 4; c++) acc[a][b][c] = 0.f;

    uint32_t offA[2], offB[2];
#pragma unroll
    for (int mi = 0; mi < 2; ++mi)
        offA[mi] = ((wm * 32 + mi * 16 + (lane & 15)) * 72 + (lane >> 4) * 8) * 2;
#pragma unroll
    for (int j = 0; j < 2; ++j)
        offB[j] = B_OFF +
            ((wn * 32 + j * 16 + (lane & 7) + ((lane >> 4) << 3)) * 72 +
             ((lane >> 3) & 1) * 8) * 2;

    uint32_t af[2][2][4], bfr[2][2][4];

    load_stage(sb, 0);
    load_stage(sb + ST_BYTES, 64);
#pragma unroll 1
    for (int s = 0; s < 8; ++s) {
        if (s < 7) CP_WAIT(1); else CP_WAIT(0);
        __syncthreads();
        if (s < 6) load_stage(sb + ((s + 2) % 3) * ST_BYTES, (s + 2) * 64);
        uint32_t cur = sb + (s % 3) * ST_BYTES;

        LDSM4(af[0][0],  cur + offA[0]);
        LDSM4(af[0][1],  cur + offA[1]);
        LDSM4(bfr[0][0], cur + offB[0]);
        LDSM4(bfr[0][1], cur + offB[1]);
#pragma unroll
        for (int ks = 0; ks < 4; ++ks) {
            const int cb = ks & 1, nb = cb ^ 1;
            if (ks < 3) {
                LDSM4(af[nb][0],  cur + offA[0] + (ks + 1) * 32);
                LDSM4(af[nb][1],  cur + offA[1] + (ks + 1) * 32);
                LDSM4(bfr[nb][0], cur + offB[0] + (ks + 1) * 32);
                LDSM4(bfr[nb][1], cur + offB[1] + (ks + 1) * 32);
            }
            MMA(acc[0][0], af[cb][0], bfr[cb][0][0], bfr[cb][0][1]);
            MMA(acc[0][1], af[cb][0], bfr[cb][0][2], bfr[cb][0][3]);
            MMA(acc[1][0], af[cb][1], bfr[cb][0][0], bfr[cb][0][1]);
            MMA(acc[1][1], af[cb][1], bfr[cb][0][2], bfr[cb][0][3]);
            MMA(acc[0][2], af[cb][0], bfr[cb][1][0], bfr[cb][1][1]);
            MMA(acc[0][3], af[cb][0], bfr[cb][1][2], bfr[cb][1][3]);
            MMA(acc[1][2], af[cb][1], bfr[cb][1][0], bfr[cb][1][1]);
            MMA(acc[1][3], af[cb][1], bfr[cb][1][2], bfr[cb][1][3]);
        }
    }
    __syncthreads();

    const float* sbias = (const float*)(smem + G23_BIAS);
    if (!is_l3) {
#pragma unroll
        for (int mi = 0; mi < 2; ++mi)
#pragma unroll
        for (int nj = 0; nj < 4; ++nj) {
            int row = m0 + wm * 32 + mi * 16 + grp;
            int cl  = wn * 32 + nj * 8 + q * 2;
            float b0 = sbias[cl], b1 = sbias[cl + 1];
            float v00 = tanhf(acc[mi][nj][0] + b0);
            float v01 = tanhf(acc[mi][nj][1] + b1);
            float v10 = tanhf(acc[mi][nj][2] + b0);
            float v11 = tanhf(acc[mi][nj][3] + b1);
            size_t o0 = (size_t)row * 512 + n0 + cl;
            *reinterpret_cast<__half2*>(O + o0) =
                __halves2half2(__float2half_rn(v00), __float2half_rn(v01));
            *reinterpret_cast<__half2*>(O + o0 + 8 * 512) =
                __halves2half2(__float2half_rn(v10), __float2half_rn(v11));
        }
    } else {
        // stage W4^T slice [64 i][128 n] fp32 into dead ring area
        float* sw4 = (float*)smem;
        for (int e = tid; e < 8192; e += 512) {
            int i = e >> 7, c = e & 127;
            sw4[i * 129 + c] = g_w4t[mlp][i * 512 + n0 + c];
        }
        __syncthreads();
        const int iA = (wm * 32 + grp) & 63;
        float ps[2][2];
        ps[0][0] = ps[0][1] = ps[1][0] = ps[1][1] = 0.f;
#pragma unroll
        for (int mi = 0; mi < 2; ++mi)
#pragma unroll
        for (int nj = 0; nj < 4; ++nj) {
            int cl = wn * 32 + nj * 8 + q * 2;
            float b0 = sbias[cl], b1 = sbias[cl + 1];
            int i0 = (iA + mi * 16) & 63, i1 = (iA + mi * 16 + 8) & 63;
            ps[mi][0] += tanhf(acc[mi][nj][0] + b0) * sw4[i0 * 129 + cl]
                       + tanhf(acc[mi][nj][1] + b1) * sw4[i0 * 129 + cl + 1];
            ps[mi][1] += tanhf(acc[mi][nj][2] + b0) * sw4[i1 * 129 + cl]
                       + tanhf(acc[mi][nj][3] + b1) * sw4[i1 * 129 + cl + 1];
        }
        int slice = blockIdx.x * 4 + wn;
#pragma unroll
        for (int mi = 0; mi < 2; ++mi)
#pragma unroll
        for (int rh = 0; rh < 2; ++rh) {
            float v = ps[mi][rh];
            v += __shfl_xor_sync(0xffffffffu, v, 1);
            v += __shfl_xor_sync(0xffffffffu, v, 2);
            if (q == 0)
                g_part[slice][m0 + wm * 32 + mi * 16 + rh * 8 + grp] = v;
        }
    }
}

// ============================================================================
// gemm_l1: K=64, Z fp16, W1 fp16, 1 product. grid (4 nCTA, 512).
// Each CTA: 4 consecutive m-tiles; B loaded once; 2-stage A ring so the
// next tile's A load overlaps compute+store of the current tile.
// 256 threads, warp tile 64x32.
// ============================================================================
__global__ __launch_bounds__(256, 2) void gemm_l1(
    const float* __restrict__ b1s, const float* __restrict__ b1t)
{
    extern __shared__ uint8_t smem[];
    const uint32_t sb = (uint32_t)__cvta_generic_to_shared(smem);
    const int tid = threadIdx.x, lane = tid & 31, wid = tid >> 5;
    const int wm = wid >> 2, wn = wid & 3;
    const int grp = lane >> 2, q = lane & 3;
    const int n0 = blockIdx.x * 128;
    const int mlp = (blockIdx.y >= 256) ? 1 : 0;
    const int grp4 = blockIdx.y & 255;            // group of 4 m-tiles

    if (tid < 128)
        ((float*)(smem + L1_BIAS))[tid] = (mlp ? b1t : b1s)[n0 + tid];

    // B once: W1^T 128n x 64k @0
#pragma unroll
    for (int i = 0; i < 4; i++) {
        int c = tid + i * 256;
        int n = c >> 3, kc = (c & 7) << 3;
        CP16(sb + (n * 72 + kc) * 2, g_w1h[mlp] + (size_t)(n0 + n) * 64 + kc);
    }
    // A tile loader (Z rows)
    auto load_a = [&](int t, int buf) {
        int zrow0 = (grp4 * 4 + t) * 128;
#pragma unroll
        for (int i = 0; i < 4; i++) {
            int c = tid + i * 256;
            int r = c >> 3, kc = (c & 7) << 3;
            CP16(sb + L1A_OFF + buf * 18432 + (r * 72 + kc) * 2,
                 g_z + (size_t)(zrow0 + r) * 64 + kc);
        }
        CP_COMMIT;
    };
    load_a(0, 0);

    uint32_t offA[4], offB[2];
#pragma unroll
    for (int mi = 0; mi < 4; ++mi)
        offA[mi] = ((wm * 64 + mi * 16 + (lane & 15)) * 72 + (lane >> 4) * 8) * 2;
#pragma unroll
    for (int j = 0; j < 2; ++j)
        offB[j] = ((wn * 32 + j * 16 + (lane & 7) + ((lane >> 4) << 3)) * 72 +
                   ((lane >> 3) & 1) * 8) * 2;

    const float* sbias = (const float*)(smem + L1_BIAS);

#pragma unroll 1
    for (int t = 0; t < 4; ++t) {
        CP_WAIT(0);
        __syncthreads();
        if (t < 3) load_a(t + 1, (t + 1) & 1);
        uint32_t cur = sb + L1A_OFF + (t & 1) * 18432;

        float acc[4][4][4];
#pragma unroll
        for (int a = 0; a < 4; a++)
#pragma unroll
            for (int b = 0; b < 4; b++)
#pragma unroll
                for (int c = 0; c < 4; c++) acc[a][b][c] = 0.f;

#pragma unroll
        for (int ks = 0; ks < 64; ks += 16) {
            uint32_t a[4][4];
#pragma unroll
            for (int mi = 0; mi < 4; ++mi) LDSM4(a[mi], cur + offA[mi] + ks * 2);
#pragma unroll
            for (int j = 0; j < 2; ++j) {
                uint32_t b[4];
                LDSM4(b, sb + offB[j] + ks * 2);
#pragma unroll
                for (int mi = 0; mi < 4; ++mi) {
                    MMA(acc[mi][j * 2],     a[mi], b[0], b[1]);
                    MMA(acc[mi][j * 2 + 1], a[mi], b[2], b[3]);
                }
            }
        }

        const int m0 = (mlp * 1024 + grp4 * 4 + t) * 128;
#pragma unroll
        for (int mi = 0; mi < 4; ++mi)
#pragma unroll
        for (int nj = 0; nj < 4; ++nj) {
            int row = m0 + wm * 64 + mi * 16 + grp;
            int cl  = wn * 32 + nj * 8 + q * 2;
            float b0 = sbias[cl], b1 = sbias[cl + 1];
            float v00 = tanhf(acc[mi][nj][0] + b0);
            float v01 = tanhf(acc[mi][nj][1] + b1);
            float v10 = tanhf(acc[mi][nj][2] + b0);
            float v11 = tanhf(acc[mi][nj][3] + b1);
            size_t o0 = (size_t)row * 512 + n0 + cl;
            *reinterpret_cast<__half2*>(g_h1 + o0) =
                __halves2half2(__float2half_rn(v00), __float2half_rn(v01));
            *reinterpret_cast<__half2*>(g_h1 + o0 + 8 * 512) =
                __halves2half2(__float2half_rn(v10), __float2half_rn(v11));
        }
    }
}

// ============================================================================
__global__ __launch_bounds__(256) void final_k(
    const float* __restrict__ x, const float* __restrict__ sb4,
    const float* __restrict__ tb4, float* __restrict__ out)
{
    int r = blockIdx.x * 256 + threadIdx.x;
    int i = r & 63;
    float ds = sb4[i], dt = tb4[i];
#pragma unroll
    for (int s = 0; s < 16; s++) {
        ds += g_part[s][r];
        dt += g_part[s][HALF_M + r];
    }
    out[r] = (x[r] - dt) * expf(-ds);
}

// ============================================================================
extern "C" void kernel_launch(void* const* d_in, const int* in_sizes, int n_in,
                              void* d_out, int out_size)
{
    (void)in_sizes; (void)n_in; (void)out_size;
    const float* x    = (const float*)d_in[0];
    const float* koop = (const float*)d_in[1];
    const float* sW1 = (const float*)d_in[2];  const float* sb1 = (const float*)d_in[3];
    const float* sW2 = (const float*)d_in[4];  const float* sb2 = (const float*)d_in[5];
    const float* sW3 = (const float*)d_in[6];  const float* sb3 = (const float*)d_in[7];
    const float* sW4 = (const float*)d_in[8];  const float* sb4 = (const float*)d_in[9];
    const float* tW1 = (const float*)d_in[10]; const float* tb1 = (const float*)d_in[11];
    const float* tW2 = (const float*)d_in[12]; const float* tb2 = (const float*)d_in[13];
    const float* tW3 = (const float*)d_in[14]; const float* tb3 = (const float*)d_in[15];
    const float* tW4 = (const float*)d_in[16]; const float* tb4 = (const float*)d_in[17];
    float* out = (float*)d_out;

    static int done = 0;
    if (!done) {
        cudaFuncSetAttribute(gemm23, cudaFuncAttributeMaxDynamicSharedMemorySize, G23_SMEM);
        cudaFuncSetAttribute(gemm_l1, cudaFuncAttributeMaxDynamicSharedMemorySize, L1_SMEM);
        done = 1;
    }

    prep_z<<<2048, 256>>>(koop);
    prep_w<<<dim3(16, 16, 7), dim3(32, 8)>>>(sW1, sW2, sW3, sW4,
                                             tW1, tW2, tW3, tW4);

    gemm_l1<<<dim3(4, 512), 256, L1_SMEM>>>(sb1, tb1);
    gemm23 <<<dim3(4, 2048), 512, G23_SMEM>>>(0, 0, sb2, tb2);
    gemm23 <<<dim3(4, 2048), 512, G23_SMEM>>>(1, 1, sb3, tb3);
    final_k<<<512, 256>>>(x, sb4, tb4, out);
}